// round 13
// baseline (speedup 1.0000x reference)
#include <cuda_runtime.h>
#include <cstdint>

// SpatialKNNEdge: for each batch b, sink row i < taus[b]:
//   sink = pos[b, T[b]+i], candidates j in [0, T[b]+taus[b])
//   top-16 smallest squared distances (stable, lowest-index ties),
//   write adj[b,i,nbr]=1 for selected nbr with nbr < i. Everything else 0.
//
// Block layout: grid(16, B), 256 threads.
//   rows owned by block bx: { i : i ≡ bx (mod 16) }  (zeroing: 128 rows, kNN: i<1024 → 64 rows)
//   threads   0..127: kNN, 2 threads per row (each scans half the candidates), merge via SMEM
//   threads 128..255: stream zeros for all 128 owned rows (1 MB, coalesced float4, streaming hint)
//   __syncthreads(), then kNN threads scatter the ones (same block owns the row → ordered).

#define NN   2048
#define FF   128
#define KK   16
#define BPB  16            // blocks per batch (row residue classes)
#define ROWS_Z 128         // NN / BPB rows zeroed per block
#define KROWS  64          // kNN rows per block (covers i < 1024; taus <= 1023)

__device__ __forceinline__ float dist2(float4 sp, float4 p) {
    float dx = sp.x - p.x;
    float dy = sp.y - p.y;
    float dz = sp.z - p.z;
    return __fmaf_rn(dx, dx, __fmaf_rn(dy, dy, dz * dz));
}

__global__ __launch_bounds__(256, 2)
void knn_adj_kernel(const float* __restrict__ nodes,
                    const int*   __restrict__ T,
                    const int*   __restrict__ taus,
                    float*       __restrict__ out)
{
    const int bx  = blockIdx.x;   // 0..15 : row residue class
    const int b   = blockIdx.y;   // batch
    const int tid = threadIdx.x;

    __shared__ float4 spos[NN];                 // candidate positions (x,y,z,0)
    __shared__ float  md[KROWS][2][KK + 1];     // per-row, per-half sorted dists (+INF sentinel)
    __shared__ unsigned short mj[KROWS][2][KK + 1];

    const int Tb = T[b];
    const int tb = taus[b];
    int maxJ = Tb + tb;
    if (maxJ > NN) maxJ = NN;

    const bool block_knn = (bx < tb);   // block-uniform: any active sink row in this block?

    const float INF_F = 1e30f;

    if (block_knn) {
        // Stage pos[b, 0:maxJ, 0:3] into shared memory.
        for (int j = tid; j < maxJ; j += 256) {
            const float* p = nodes + ((size_t)(b * NN + j)) * FF;
            spos[j] = make_float4(__ldg(p + 0), __ldg(p + 1), __ldg(p + 2), 0.0f);
        }
        __syncthreads();
    }

    // ---- kNN phase: threads 0..127, two threads (halves) per row ----
    float rd[KK];
    int   rj[KK];
    int   i_row = 0;
    bool  emit  = false;

    if (block_knn && tid < 128) {
        const int k = tid >> 1;      // local row 0..63
        const int h = tid & 1;       // which half of the scan
        const int i = bx + BPB * k;  // global sink row (<= 1023)

        if (i < tb) {
            const int sg = Tb + i;   // sink node index; < maxJ <= 2046 < NN (no clip binds)
            const float4 sp = spos[sg];

            float bd[KK];
            int   bi[KK];
            #pragma unroll
            for (int s = 0; s < KK; ++s) { bd[s] = INF_F; bi[s] = 0xFFFF; }

            const int half = maxJ >> 1;
            const int j0 = h ? half : 0;
            const int j1 = h ? maxJ : half;

            for (int j = j0; j < j1; ++j) {
                const float d2 = dist2(sp, spos[j]);
                if (d2 < bd[KK - 1]) {
                    // stable insertion (strict <): equal dists keep earlier j first
                    bool cs = true;                       // c_{KK-1} guaranteed by guard
                    #pragma unroll
                    for (int s = KK - 1; s >= 1; --s) {
                        const bool cm = d2 < bd[s - 1];   // c_{s-1}
                        const float nv = cm ? bd[s - 1] : d2;
                        const int   ni = cm ? bi[s - 1] : j;
                        bd[s] = cs ? nv : bd[s];
                        bi[s] = cs ? ni : bi[s];
                        cs = cm;
                    }
                    if (cs) { bd[0] = d2; bi[0] = j; }
                }
            }

            #pragma unroll
            for (int s = 0; s < KK; ++s) {
                md[k][h][s] = bd[s];
                mj[k][h][s] = (unsigned short)bi[s];
            }
            md[k][h][KK] = INF_F;          // sentinel for the merge
            mj[k][h][KK] = 0xFFFF;
        }
        __syncwarp(0xFFFFFFFF);

        // Even thread merges the two sorted 16-lists (lexicographic (d, j) → stable top-k).
        if (i < tb && h == 0) {
            int pa = 0, pb = 0;
            #pragma unroll
            for (int s = 0; s < KK; ++s) {
                const float da = md[k][0][pa];
                const float db = md[k][1][pb];
                const int   ja = mj[k][0][pa];
                const int   jb = mj[k][1][pb];
                const bool ta = (da < db) || (da == db && ja < jb);
                rd[s] = ta ? da : db;
                rj[s] = ta ? ja : jb;
                pa += ta ? 1 : 0;
                pb += ta ? 0 : 1;
            }
            i_row = i;
            emit = true;
        }
    }

    // ---- Zero phase: threads 128..255 stream zeros for all 128 owned rows ----
    if (tid >= 128) {
        const int t2 = tid - 128;
        const float4 z = make_float4(0.0f, 0.0f, 0.0f, 0.0f);
        for (int k = 0; k < ROWS_Z; ++k) {
            const int r = bx + BPB * k;
            float4* rowp = reinterpret_cast<float4*>(out + ((size_t)(b * NN + r)) * NN);
            #pragma unroll 4
            for (int c = t2; c < NN / 4; c += 128) {
                __stcs(rowp + c, z);
            }
        }
    }

    __syncthreads();   // orders zeros before ones (same block owns every touched row)

    // ---- Scatter ones: top-k entries that are real (d < INF) and causal (nbr < i) ----
    if (emit) {
        const size_t base = ((size_t)(b * NN + i_row)) * NN;
        #pragma unroll
        for (int s = 0; s < KK; ++s) {
            if (rd[s] < INF_F && rj[s] < i_row) {
                out[base + rj[s]] = 1.0f;
            }
        }
    }
}

extern "C" void kernel_launch(void* const* d_in, const int* in_sizes, int n_in,
                              void* d_out, int out_size) {
    const float* nodes = (const float*)d_in[0];
    const int*   T     = (const int*)  d_in[1];
    const int*   taus  = (const int*)  d_in[2];
    float*       out   = (float*)      d_out;

    const int B = in_sizes[1];   // length of T

    dim3 grid(BPB, B);
    knn_adj_kernel<<<grid, 256>>>(nodes, T, taus, out);
}

// round 14
// speedup vs baseline: 1.0053x; 1.0053x over previous
#include <cuda_runtime.h>
#include <cstdint>

// SpatialKNNEdge: for each batch b, sink row i < taus[b]:
//   sink = pos[b, T[b]+i], candidates j in [0, T[b]+taus[b])
//   top-16 smallest squared distances (stable, lowest-index ties),
//   write adj[b,i,nbr]=1 for selected nbr with nbr < i. Everything else 0.
//
// Block layout: grid(16, B), 256 threads.
//   rows owned by block bx: { i : i ≡ bx (mod 16) }  (zeroing: 128 rows, kNN: i<1024 → 64 rows)
//   threads   0..127: kNN, 2 threads per row (each scans half the candidates), merge via SMEM
//   threads 128..255: stream zeros for all 128 owned rows (1 MB, coalesced float4, streaming hint)
//   __syncthreads(), then kNN threads scatter the ones (same block owns the row → ordered).

#define NN   2048
#define FF   128
#define KK   16
#define BPB  16            // blocks per batch (row residue classes)
#define ROWS_Z 128         // NN / BPB rows zeroed per block
#define KROWS  64          // kNN rows per block (covers i < 1024; taus <= 1023)

__device__ __forceinline__ float dist2(float4 sp, float4 p) {
    float dx = sp.x - p.x;
    float dy = sp.y - p.y;
    float dz = sp.z - p.z;
    return __fmaf_rn(dx, dx, __fmaf_rn(dy, dy, dz * dz));
}

__global__ __launch_bounds__(256, 2)
void knn_adj_kernel(const float* __restrict__ nodes,
                    const int*   __restrict__ T,
                    const int*   __restrict__ taus,
                    float*       __restrict__ out)
{
    const int bx  = blockIdx.x;   // 0..15 : row residue class
    const int b   = blockIdx.y;   // batch
    const int tid = threadIdx.x;

    __shared__ float4 spos[NN];                 // candidate positions (x,y,z,0)
    __shared__ float  md[KROWS][2][KK + 1];     // per-row, per-half sorted dists (+INF sentinel)
    __shared__ unsigned short mj[KROWS][2][KK + 1];

    const int Tb = T[b];
    const int tb = taus[b];
    int maxJ = Tb + tb;
    if (maxJ > NN) maxJ = NN;

    const bool block_knn = (bx < tb);   // block-uniform: any active sink row in this block?

    const float INF_F = 1e30f;

    if (block_knn) {
        // Stage pos[b, 0:maxJ, 0:3] into shared memory.
        for (int j = tid; j < maxJ; j += 256) {
            const float* p = nodes + ((size_t)(b * NN + j)) * FF;
            spos[j] = make_float4(__ldg(p + 0), __ldg(p + 1), __ldg(p + 2), 0.0f);
        }
        __syncthreads();
    }

    // ---- kNN phase: threads 0..127, two threads (halves) per row ----
    float rd[KK];
    int   rj[KK];
    int   i_row = 0;
    bool  emit  = false;

    if (block_knn && tid < 128) {
        const int k = tid >> 1;      // local row 0..63
        const int h = tid & 1;       // which half of the scan
        const int i = bx + BPB * k;  // global sink row (<= 1023)

        if (i < tb) {
            const int sg = Tb + i;   // sink node index; < maxJ <= 2046 < NN (no clip binds)
            const float4 sp = spos[sg];

            float bd[KK];
            int   bi[KK];
            #pragma unroll
            for (int s = 0; s < KK; ++s) { bd[s] = INF_F; bi[s] = 0xFFFF; }

            const int half = maxJ >> 1;
            const int j0 = h ? half : 0;
            const int j1 = h ? maxJ : half;

            for (int j = j0; j < j1; ++j) {
                const float d2 = dist2(sp, spos[j]);
                if (d2 < bd[KK - 1]) {
                    // stable insertion (strict <): equal dists keep earlier j first
                    bool cs = true;                       // c_{KK-1} guaranteed by guard
                    #pragma unroll
                    for (int s = KK - 1; s >= 1; --s) {
                        const bool cm = d2 < bd[s - 1];   // c_{s-1}
                        const float nv = cm ? bd[s - 1] : d2;
                        const int   ni = cm ? bi[s - 1] : j;
                        bd[s] = cs ? nv : bd[s];
                        bi[s] = cs ? ni : bi[s];
                        cs = cm;
                    }
                    if (cs) { bd[0] = d2; bi[0] = j; }
                }
            }

            #pragma unroll
            for (int s = 0; s < KK; ++s) {
                md[k][h][s] = bd[s];
                mj[k][h][s] = (unsigned short)bi[s];
            }
            md[k][h][KK] = INF_F;          // sentinel for the merge
            mj[k][h][KK] = 0xFFFF;
        }
        __syncwarp(0xFFFFFFFF);

        // Even thread merges the two sorted 16-lists (lexicographic (d, j) → stable top-k).
        if (i < tb && h == 0) {
            int pa = 0, pb = 0;
            #pragma unroll
            for (int s = 0; s < KK; ++s) {
                const float da = md[k][0][pa];
                const float db = md[k][1][pb];
                const int   ja = mj[k][0][pa];
                const int   jb = mj[k][1][pb];
                const bool ta = (da < db) || (da == db && ja < jb);
                rd[s] = ta ? da : db;
                rj[s] = ta ? ja : jb;
                pa += ta ? 1 : 0;
                pb += ta ? 0 : 1;
            }
            i_row = i;
            emit = true;
        }
    }

    // ---- Zero phase: threads 128..255 stream zeros for all 128 owned rows ----
    if (tid >= 128) {
        const int t2 = tid - 128;
        const float4 z = make_float4(0.0f, 0.0f, 0.0f, 0.0f);
        for (int k = 0; k < ROWS_Z; ++k) {
            const int r = bx + BPB * k;
            float4* rowp = reinterpret_cast<float4*>(out + ((size_t)(b * NN + r)) * NN);
            #pragma unroll 4
            for (int c = t2; c < NN / 4; c += 128) {
                __stcs(rowp + c, z);
            }
        }
    }

    __syncthreads();   // orders zeros before ones (same block owns every touched row)

    // ---- Scatter ones: top-k entries that are real (d < INF) and causal (nbr < i) ----
    if (emit) {
        const size_t base = ((size_t)(b * NN + i_row)) * NN;
        #pragma unroll
        for (int s = 0; s < KK; ++s) {
            if (rd[s] < INF_F && rj[s] < i_row) {
                out[base + rj[s]] = 1.0f;
            }
        }
    }
}

extern "C" void kernel_launch(void* const* d_in, const int* in_sizes, int n_in,
                              void* d_out, int out_size) {
    const float* nodes = (const float*)d_in[0];
    const int*   T     = (const int*)  d_in[1];
    const int*   taus  = (const int*)  d_in[2];
    float*       out   = (float*)      d_out;

    const int B = in_sizes[1];   // length of T

    dim3 grid(BPB, B);
    knn_adj_kernel<<<grid, 256>>>(nodes, T, taus, out);
}